// round 1
// baseline (speedup 1.0000x reference)
#include <cuda_runtime.h>
#include <cuda_bf16.h>

#define N_NODES 100000
#define N_EDGES 3200000

// Scratch (device globals — no allocation allowed)
__device__ float    g_agg1m[2 * N_NODES];
__device__ unsigned g_agg1x[2 * N_NODES];
__device__ float    g_h1   [32 * N_NODES];
__device__ float    g_agg2m[32 * N_NODES];
__device__ unsigned g_agg2x[32 * N_NODES];

// Order-preserving float<->uint encoding (for atomicMax over signed floats)
__device__ __forceinline__ unsigned fenc(float f) {
    unsigned u = __float_as_uint(f);
    return (u & 0x80000000u) ? ~u : (u | 0x80000000u);
}
__device__ __forceinline__ float fdec(unsigned u) {
    u = (u & 0x80000000u) ? (u & 0x7FFFFFFFu) : ~u;
    return __uint_as_float(u);
}

// ---------------------------------------------------------------------------
// Init layer-1 accumulators. 0u is an impossible fenc() output for real
// inputs, so it doubles as the "no edge" sentinel.
__global__ void k_init1() {
    int i = blockIdx.x * blockDim.x + threadIdx.x;
    if (i < 2 * N_NODES) { g_agg1m[i] = 0.0f; g_agg1x[i] = 0u; }
}

// ---------------------------------------------------------------------------
// Layer-1 edge scatter: dim-2 messages. x table is 800KB -> L2/L1 resident.
__global__ void k_edge1(const int* __restrict__ ei,
                        const float* __restrict__ norm,
                        const float* __restrict__ x) {
    int e = blockIdx.x * blockDim.x + threadIdx.x;
    if (e >= N_EDGES) return;
    int s = ei[e];
    int d = ei[N_EDGES + e];
    float w = norm[e];
    float2 xv = __ldg((const float2*)x + s);
    atomicAdd(&g_agg1m[2 * d + 0], xv.x * w);
    atomicAdd(&g_agg1m[2 * d + 1], xv.y * w);
    atomicMax(&g_agg1x[2 * d + 0], fenc(xv.x));
    atomicMax(&g_agg1x[2 * d + 1], fenc(xv.y));
}

// ---------------------------------------------------------------------------
// Layer-1 node update: h1[i] = concat(relu(WSAGE), relu(MSAGE))  [N,32]
// Also zeroes layer-2 accumulators (agg2x bits=0 == float 0, valid since
// layer-2 messages are post-ReLU nonnegative).
__global__ void k_node1(const float* __restrict__ x,
                        const float* __restrict__ w1m_l, const float* __restrict__ b1m,
                        const float* __restrict__ w1m_r,
                        const float* __restrict__ w1x_l, const float* __restrict__ b1x,
                        const float* __restrict__ w1x_r) {
    __shared__ float s_wml[48], s_bm[24], s_wmr[48], s_wxl[16], s_bx[8], s_wxr[16];
    int t = threadIdx.x;
    if (t < 48) { s_wml[t] = w1m_l[t]; s_wmr[t] = w1m_r[t]; }
    if (t < 24) s_bm[t] = b1m[t];
    if (t < 16) { s_wxl[t] = w1x_l[t]; s_wxr[t] = w1x_r[t]; }
    if (t < 8)  s_bx[t]  = b1x[t];
    __syncthreads();

    int i = blockIdx.x * blockDim.x + t;
    if (i >= N_NODES) return;

    float a0 = g_agg1m[2 * i], a1 = g_agg1m[2 * i + 1];
    unsigned e0 = g_agg1x[2 * i], e1 = g_agg1x[2 * i + 1];
    float m0 = e0 ? fdec(e0) : 0.0f;
    float m1 = e1 ? fdec(e1) : 0.0f;
    float2 xv = __ldg((const float2*)x + i);

    float h[32];
#pragma unroll
    for (int k = 0; k < 24; k++) {
        float v = fmaf(a0, s_wml[2 * k], fmaf(a1, s_wml[2 * k + 1],
                  fmaf(xv.x, s_wmr[2 * k], fmaf(xv.y, s_wmr[2 * k + 1], s_bm[k]))));
        h[k] = fmaxf(v, 0.0f);
    }
#pragma unroll
    for (int k = 0; k < 8; k++) {
        float v = fmaf(m0, s_wxl[2 * k], fmaf(m1, s_wxl[2 * k + 1],
                  fmaf(xv.x, s_wxr[2 * k], fmaf(xv.y, s_wxr[2 * k + 1], s_bx[k]))));
        h[24 + k] = fmaxf(v, 0.0f);
    }

    float4* hp = (float4*)&g_h1[32 * i];
    float4* am = (float4*)&g_agg2m[32 * i];
    float4* ax = (float4*)&g_agg2x[32 * i];
    float4 z = make_float4(0.f, 0.f, 0.f, 0.f);
#pragma unroll
    for (int q = 0; q < 8; q++) {
        hp[q] = make_float4(h[4 * q], h[4 * q + 1], h[4 * q + 2], h[4 * q + 3]);
        am[q] = z;
        ax[q] = z;
    }
}

// ---------------------------------------------------------------------------
// Layer-2 edge scatter: 8 lanes per edge, one float4 of the 32-dim row each.
// Sum via vectorized red.global.add.v4.f32, max via raw-bit u32 RED (values>=0).
__global__ void k_edge2(const int* __restrict__ ei, const float* __restrict__ norm) {
    int tid = blockIdx.x * blockDim.x + threadIdx.x;
    if (tid >= N_EDGES * 8) return;
    int e = tid >> 3;
    int p = tid & 7;
    int s = ei[e];
    int d = ei[N_EDGES + e];
    float w = norm[e];
    float4 v = *(const float4*)&g_h1[32 * s + 4 * p];
    float* dm = &g_agg2m[32 * d + 4 * p];
    asm volatile("red.global.add.v4.f32 [%0], {%1, %2, %3, %4};"
                 :: "l"(dm), "f"(v.x * w), "f"(v.y * w), "f"(v.z * w), "f"(v.w * w)
                 : "memory");
    unsigned* dx = &g_agg2x[32 * d + 4 * p];
    atomicMax(dx + 0, __float_as_uint(v.x));
    atomicMax(dx + 1, __float_as_uint(v.y));
    atomicMax(dx + 2, __float_as_uint(v.z));
    atomicMax(dx + 3, __float_as_uint(v.w));
}

// ---------------------------------------------------------------------------
// Layer-2 node update + MLP head, fused.
__global__ void k_node2(const float* __restrict__ w2m_l, const float* __restrict__ b2m,
                        const float* __restrict__ w2m_r,
                        const float* __restrict__ w2x_l, const float* __restrict__ b2x,
                        const float* __restrict__ w2x_r,
                        const float* __restrict__ w3, const float* __restrict__ b3,
                        const float* __restrict__ w4, const float* __restrict__ b4,
                        const float* __restrict__ w5, const float* __restrict__ b5,
                        float* __restrict__ out) {
    __shared__ float s_w2ml[384], s_w2mr[384], s_w2xl[128], s_w2xr[128];
    __shared__ float s_b2m[12], s_b2x[4], s_w3[128], s_b3[8], s_w4[40], s_b4[5], s_w5[5], s_b5[1];
    int t = threadIdx.x;
    for (int i = t; i < 384; i += blockDim.x) { s_w2ml[i] = w2m_l[i]; s_w2mr[i] = w2m_r[i]; }
    for (int i = t; i < 128; i += blockDim.x) { s_w2xl[i] = w2x_l[i]; s_w2xr[i] = w2x_r[i]; s_w3[i] = w3[i]; }
    if (t < 12) s_b2m[t] = b2m[t];
    if (t < 4)  s_b2x[t] = b2x[t];
    if (t < 8)  s_b3[t]  = b3[t];
    if (t < 40) s_w4[t]  = w4[t];
    if (t < 5)  { s_b4[t] = b4[t]; s_w5[t] = w5[t]; }
    if (t == 0) s_b5[0] = b5[0];
    __syncthreads();

    int i = blockIdx.x * blockDim.x + t;
    if (i >= N_NODES) return;

    float h1v[32];
    const float4* hp = (const float4*)&g_h1[32 * i];
#pragma unroll
    for (int q = 0; q < 8; q++) {
        float4 v = hp[q];
        h1v[4 * q] = v.x; h1v[4 * q + 1] = v.y; h1v[4 * q + 2] = v.z; h1v[4 * q + 3] = v.w;
    }

    float h2[16];
    // mean branch (12 outputs): lin_l(agg2m) + lin_r(h1)
    {
        float acc[12];
#pragma unroll
        for (int k = 0; k < 12; k++) {
            float a = s_b2m[k];
#pragma unroll
            for (int j = 0; j < 32; j++) a = fmaf(h1v[j], s_w2mr[k * 32 + j], a);
            acc[k] = a;
        }
        const float4* ap = (const float4*)&g_agg2m[32 * i];
#pragma unroll
        for (int q = 0; q < 8; q++) {
            float4 v = ap[q];
#pragma unroll
            for (int k = 0; k < 12; k++) {
                acc[k] = fmaf(v.x, s_w2ml[k * 32 + 4 * q + 0],
                         fmaf(v.y, s_w2ml[k * 32 + 4 * q + 1],
                         fmaf(v.z, s_w2ml[k * 32 + 4 * q + 2],
                         fmaf(v.w, s_w2ml[k * 32 + 4 * q + 3], acc[k]))));
            }
        }
#pragma unroll
        for (int k = 0; k < 12; k++) h2[k] = fmaxf(acc[k], 0.0f);
    }
    // max branch (4 outputs): lin_l(agg2x) + lin_r(h1)
    {
        float acc[4];
#pragma unroll
        for (int k = 0; k < 4; k++) {
            float a = s_b2x[k];
#pragma unroll
            for (int j = 0; j < 32; j++) a = fmaf(h1v[j], s_w2xr[k * 32 + j], a);
            acc[k] = a;
        }
        const float4* xp = (const float4*)&g_agg2x[32 * i];  // bits are nonneg floats
#pragma unroll
        for (int q = 0; q < 8; q++) {
            float4 v = xp[q];
#pragma unroll
            for (int k = 0; k < 4; k++) {
                acc[k] = fmaf(v.x, s_w2xl[k * 32 + 4 * q + 0],
                         fmaf(v.y, s_w2xl[k * 32 + 4 * q + 1],
                         fmaf(v.z, s_w2xl[k * 32 + 4 * q + 2],
                         fmaf(v.w, s_w2xl[k * 32 + 4 * q + 3], acc[k]))));
            }
        }
#pragma unroll
        for (int k = 0; k < 4; k++) h2[12 + k] = fmaxf(acc[k], 0.0f);
    }

    // MLP head 16 -> 8 -> 5 -> 1
    float h3[8];
#pragma unroll
    for (int k = 0; k < 8; k++) {
        float a = s_b3[k];
#pragma unroll
        for (int j = 0; j < 16; j++) a = fmaf(h2[j], s_w3[k * 16 + j], a);
        h3[k] = fmaxf(a, 0.0f);
    }
    float h4[5];
#pragma unroll
    for (int k = 0; k < 5; k++) {
        float a = s_b4[k];
#pragma unroll
        for (int j = 0; j < 8; j++) a = fmaf(h3[j], s_w4[k * 8 + j], a);
        h4[k] = fmaxf(a, 0.0f);
    }
    float o = s_b5[0];
#pragma unroll
    for (int j = 0; j < 5; j++) o = fmaf(h4[j], s_w5[j], o);
    out[i] = o;
}

// ---------------------------------------------------------------------------
extern "C" void kernel_launch(void* const* d_in, const int* in_sizes, int n_in,
                              void* d_out, int out_size) {
    const float* x     = (const float*)d_in[0];
    const int*   ei    = (const int*)  d_in[1];
    const float* norm  = (const float*)d_in[2];
    const float* w1m_l = (const float*)d_in[3];
    const float* b1m   = (const float*)d_in[4];
    const float* w1m_r = (const float*)d_in[5];
    const float* w1x_l = (const float*)d_in[6];
    const float* b1x   = (const float*)d_in[7];
    const float* w1x_r = (const float*)d_in[8];
    const float* w2m_l = (const float*)d_in[9];
    const float* b2m   = (const float*)d_in[10];
    const float* w2m_r = (const float*)d_in[11];
    const float* w2x_l = (const float*)d_in[12];
    const float* b2x   = (const float*)d_in[13];
    const float* w2x_r = (const float*)d_in[14];
    const float* w3    = (const float*)d_in[15];
    const float* b3    = (const float*)d_in[16];
    const float* w4    = (const float*)d_in[17];
    const float* b4    = (const float*)d_in[18];
    const float* w5    = (const float*)d_in[19];
    const float* b5    = (const float*)d_in[20];
    float* out = (float*)d_out;

    k_init1<<<(2 * N_NODES + 255) / 256, 256>>>();
    k_edge1<<<(N_EDGES + 255) / 256, 256>>>(ei, norm, x);
    k_node1<<<(N_NODES + 127) / 128, 128>>>(x, w1m_l, b1m, w1m_r, w1x_l, b1x, w1x_r);
    k_edge2<<<(N_EDGES * 8 + 255) / 256, 256>>>(ei, norm);
    k_node2<<<(N_NODES + 127) / 128, 128>>>(w2m_l, b2m, w2m_r, w2x_l, b2x, w2x_r,
                                            w3, b3, w4, b4, w5, b5, out);
}

// round 2
// speedup vs baseline: 2.0787x; 2.0787x over previous
#include <cuda_runtime.h>
#include <cuda_bf16.h>

#define N_NODES 100000
#define N_EDGES 3200000
#define SCAN_B  1024
#define NBLK    ((N_NODES + SCAN_B - 1) / SCAN_B)   // 98

// ---- Scratch (device globals; no allocation allowed) ----------------------
__device__ int   g_deg [N_NODES];
__device__ int   g_off [N_NODES + 1];
__device__ int   g_pos [N_NODES];
__device__ int   g_bsum[NBLK];
__device__ int2  g_edge[N_EDGES];       // {src, float_bits(norm)} grouped by dst
__device__ float g_h1   [32 * N_NODES];
__device__ float g_agg2m[32 * N_NODES];
__device__ float g_agg2x[32 * N_NODES];

// ===========================================================================
// CSR build: count -> scan -> scatter
// ===========================================================================
__global__ void k_zero_deg() {
    int i = blockIdx.x * blockDim.x + threadIdx.x;
    if (i < N_NODES) g_deg[i] = 0;
}

__global__ void k_count(const int* __restrict__ ei) {
    int e = blockIdx.x * blockDim.x + threadIdx.x;
    if (e < N_EDGES) atomicAdd(&g_deg[ei[N_EDGES + e]], 1);
}

// Per-block exclusive scan; block totals to g_bsum.
__global__ void k_scan1() {
    __shared__ int s[SCAN_B];
    int tid = threadIdx.x;
    int i = blockIdx.x * SCAN_B + tid;
    int v = (i < N_NODES) ? g_deg[i] : 0;
    s[tid] = v;
    __syncthreads();
#pragma unroll
    for (int d = 1; d < SCAN_B; d <<= 1) {
        int t = (tid >= d) ? s[tid - d] : 0;
        __syncthreads();
        if (tid >= d) s[tid] += t;
        __syncthreads();
    }
    if (i < N_NODES) g_off[i] = s[tid] - v;           // exclusive within block
    if (tid == SCAN_B - 1) g_bsum[blockIdx.x] = s[SCAN_B - 1];
}

// Exclusive scan of NBLK block totals (single block).
__global__ void k_scan2() {
    __shared__ int s[128];
    int tid = threadIdx.x;
    int v = (tid < NBLK) ? g_bsum[tid] : 0;
    s[tid] = v;
    __syncthreads();
#pragma unroll
    for (int d = 1; d < 128; d <<= 1) {
        int t = (tid >= d) ? s[tid - d] : 0;
        __syncthreads();
        if (tid >= d) s[tid] += t;
        __syncthreads();
    }
    if (tid < NBLK) g_bsum[tid] = s[tid] - v;
}

// Add block offsets; init scatter cursors; close the offset array.
__global__ void k_scan3() {
    int i = blockIdx.x * blockDim.x + threadIdx.x;
    if (i < N_NODES) {
        int o = g_off[i] + g_bsum[i / SCAN_B];
        g_off[i] = o;
        g_pos[i] = o;
    }
    if (i == 0) g_off[N_NODES] = N_EDGES;
}

__global__ void k_scatter(const int* __restrict__ ei, const float* __restrict__ norm) {
    int e = blockIdx.x * blockDim.x + threadIdx.x;
    if (e >= N_EDGES) return;
    int s = ei[e];
    int d = ei[N_EDGES + e];
    float w = norm[e];
    int p = atomicAdd(&g_pos[d], 1);
    g_edge[p] = make_int2(s, __float_as_int(w));
}

// ===========================================================================
// Layer 1: gather (sum+max over dim-2 neighbors) fused with node GEMM.
// One warp per node; lane l writes h1 output dim l (exactly 32 dims).
// ===========================================================================
__global__ void k_layer1(const float* __restrict__ x,
                         const float* __restrict__ w1m_l, const float* __restrict__ b1m,
                         const float* __restrict__ w1m_r,
                         const float* __restrict__ w1x_l, const float* __restrict__ b1x,
                         const float* __restrict__ w1x_r) {
    __shared__ float s_wml[48], s_bm[24], s_wmr[48], s_wxl[16], s_bx[8], s_wxr[16];
    int t = threadIdx.x;
    if (t < 48) { s_wml[t] = w1m_l[t]; s_wmr[t] = w1m_r[t]; }
    if (t < 24) s_bm[t] = b1m[t];
    if (t < 16) { s_wxl[t] = w1x_l[t]; s_wxr[t] = w1x_r[t]; }
    if (t < 8)  s_bx[t]  = b1x[t];
    __syncthreads();

    int node = (blockIdx.x * blockDim.x + t) >> 5;
    int lane = t & 31;
    if (node >= N_NODES) return;

    int beg = g_off[node], end = g_off[node + 1];
    float s0 = 0.f, s1 = 0.f, m0 = -INFINITY, m1 = -INFINITY;
    for (int j = beg + lane; j < end; j += 32) {
        int2 er = g_edge[j];
        float w = __int_as_float(er.y);
        float2 xv = __ldg((const float2*)x + er.x);
        s0 = fmaf(xv.x, w, s0);
        s1 = fmaf(xv.y, w, s1);
        m0 = fmaxf(m0, xv.x);
        m1 = fmaxf(m1, xv.y);
    }
#pragma unroll
    for (int o = 16; o; o >>= 1) {
        s0 += __shfl_xor_sync(0xffffffffu, s0, o);
        s1 += __shfl_xor_sync(0xffffffffu, s1, o);
        m0 = fmaxf(m0, __shfl_xor_sync(0xffffffffu, m0, o));
        m1 = fmaxf(m1, __shfl_xor_sync(0xffffffffu, m1, o));
    }
    if (beg == end) { m0 = 0.f; m1 = 0.f; }   // empty segment -> 0 (PyG)

    float2 xv = __ldg((const float2*)x + node);
    float v;
    if (lane < 24) {
        v = fmaf(s0, s_wml[2 * lane], fmaf(s1, s_wml[2 * lane + 1],
            fmaf(xv.x, s_wmr[2 * lane], fmaf(xv.y, s_wmr[2 * lane + 1], s_bm[lane]))));
    } else {
        int p = lane - 24;
        v = fmaf(m0, s_wxl[2 * p], fmaf(m1, s_wxl[2 * p + 1],
            fmaf(xv.x, s_wxr[2 * p], fmaf(xv.y, s_wxr[2 * p + 1], s_bx[p]))));
    }
    g_h1[32 * node + lane] = fmaxf(v, 0.0f);
}

// ===========================================================================
// Layer 2 gather: 8 lanes per node, each owns one float4 of the 32-dim row.
// Register sum/max; h1 is post-ReLU >= 0 so max init 0 matches PyG semantics.
// ===========================================================================
__global__ void k_gather2() {
    int tid = blockIdx.x * blockDim.x + threadIdx.x;
    int node = tid >> 3;
    int p = tid & 7;
    if (node >= N_NODES) return;

    int beg = g_off[node], end = g_off[node + 1];
    float4 sm = make_float4(0.f, 0.f, 0.f, 0.f);
    float4 mx = make_float4(0.f, 0.f, 0.f, 0.f);

    if (beg < end) {
        int2 er = g_edge[beg];                 // prefetch
        for (int j = beg; j < end; j++) {
            int2 ernext = (j + 1 < end) ? g_edge[j + 1] : er;
            float w = __int_as_float(er.y);
            float4 v = *(const float4*)&g_h1[32 * er.x + 4 * p];
            sm.x = fmaf(v.x, w, sm.x);
            sm.y = fmaf(v.y, w, sm.y);
            sm.z = fmaf(v.z, w, sm.z);
            sm.w = fmaf(v.w, w, sm.w);
            mx.x = fmaxf(mx.x, v.x);
            mx.y = fmaxf(mx.y, v.y);
            mx.z = fmaxf(mx.z, v.z);
            mx.w = fmaxf(mx.w, v.w);
            er = ernext;
        }
    }
    *(float4*)&g_agg2m[32 * node + 4 * p] = sm;
    *(float4*)&g_agg2x[32 * node + 4 * p] = mx;
}

// ===========================================================================
// Layer-2 node update + MLP head, fused.
// ===========================================================================
__global__ void k_node2(const float* __restrict__ w2m_l, const float* __restrict__ b2m,
                        const float* __restrict__ w2m_r,
                        const float* __restrict__ w2x_l, const float* __restrict__ b2x,
                        const float* __restrict__ w2x_r,
                        const float* __restrict__ w3, const float* __restrict__ b3,
                        const float* __restrict__ w4, const float* __restrict__ b4,
                        const float* __restrict__ w5, const float* __restrict__ b5,
                        float* __restrict__ out) {
    __shared__ float s_w2ml[384], s_w2mr[384], s_w2xl[128], s_w2xr[128];
    __shared__ float s_b2m[12], s_b2x[4], s_w3[128], s_b3[8], s_w4[40], s_b4[5], s_w5[5], s_b5[1];
    int t = threadIdx.x;
    for (int i = t; i < 384; i += blockDim.x) { s_w2ml[i] = w2m_l[i]; s_w2mr[i] = w2m_r[i]; }
    for (int i = t; i < 128; i += blockDim.x) { s_w2xl[i] = w2x_l[i]; s_w2xr[i] = w2x_r[i]; s_w3[i] = w3[i]; }
    if (t < 12) s_b2m[t] = b2m[t];
    if (t < 4)  s_b2x[t] = b2x[t];
    if (t < 8)  s_b3[t]  = b3[t];
    if (t < 40) s_w4[t]  = w4[t];
    if (t < 5)  { s_b4[t] = b4[t]; s_w5[t] = w5[t]; }
    if (t == 0) s_b5[0] = b5[0];
    __syncthreads();

    int i = blockIdx.x * blockDim.x + t;
    if (i >= N_NODES) return;

    float h1v[32];
    const float4* hp = (const float4*)&g_h1[32 * i];
#pragma unroll
    for (int q = 0; q < 8; q++) {
        float4 v = hp[q];
        h1v[4 * q] = v.x; h1v[4 * q + 1] = v.y; h1v[4 * q + 2] = v.z; h1v[4 * q + 3] = v.w;
    }

    float h2[16];
    {
        float acc[12];
#pragma unroll
        for (int k = 0; k < 12; k++) {
            float a = s_b2m[k];
#pragma unroll
            for (int j = 0; j < 32; j++) a = fmaf(h1v[j], s_w2mr[k * 32 + j], a);
            acc[k] = a;
        }
        const float4* ap = (const float4*)&g_agg2m[32 * i];
#pragma unroll
        for (int q = 0; q < 8; q++) {
            float4 v = ap[q];
#pragma unroll
            for (int k = 0; k < 12; k++) {
                acc[k] = fmaf(v.x, s_w2ml[k * 32 + 4 * q + 0],
                         fmaf(v.y, s_w2ml[k * 32 + 4 * q + 1],
                         fmaf(v.z, s_w2ml[k * 32 + 4 * q + 2],
                         fmaf(v.w, s_w2ml[k * 32 + 4 * q + 3], acc[k]))));
            }
        }
#pragma unroll
        for (int k = 0; k < 12; k++) h2[k] = fmaxf(acc[k], 0.0f);
    }
    {
        float acc[4];
#pragma unroll
        for (int k = 0; k < 4; k++) {
            float a = s_b2x[k];
#pragma unroll
            for (int j = 0; j < 32; j++) a = fmaf(h1v[j], s_w2xr[k * 32 + j], a);
            acc[k] = a;
        }
        const float4* xp = (const float4*)&g_agg2x[32 * i];
#pragma unroll
        for (int q = 0; q < 8; q++) {
            float4 v = xp[q];
#pragma unroll
            for (int k = 0; k < 4; k++) {
                acc[k] = fmaf(v.x, s_w2xl[k * 32 + 4 * q + 0],
                         fmaf(v.y, s_w2xl[k * 32 + 4 * q + 1],
                         fmaf(v.z, s_w2xl[k * 32 + 4 * q + 2],
                         fmaf(v.w, s_w2xl[k * 32 + 4 * q + 3], acc[k]))));
            }
        }
#pragma unroll
        for (int k = 0; k < 4; k++) h2[12 + k] = fmaxf(acc[k], 0.0f);
    }

    float h3[8];
#pragma unroll
    for (int k = 0; k < 8; k++) {
        float a = s_b3[k];
#pragma unroll
        for (int j = 0; j < 16; j++) a = fmaf(h2[j], s_w3[k * 16 + j], a);
        h3[k] = fmaxf(a, 0.0f);
    }
    float h4[5];
#pragma unroll
    for (int k = 0; k < 5; k++) {
        float a = s_b4[k];
#pragma unroll
        for (int j = 0; j < 8; j++) a = fmaf(h3[j], s_w4[k * 8 + j], a);
        h4[k] = fmaxf(a, 0.0f);
    }
    float o = s_b5[0];
#pragma unroll
    for (int j = 0; j < 5; j++) o = fmaf(h4[j], s_w5[j], o);
    out[i] = o;
}

// ---------------------------------------------------------------------------
extern "C" void kernel_launch(void* const* d_in, const int* in_sizes, int n_in,
                              void* d_out, int out_size) {
    const float* x     = (const float*)d_in[0];
    const int*   ei    = (const int*)  d_in[1];
    const float* norm  = (const float*)d_in[2];
    const float* w1m_l = (const float*)d_in[3];
    const float* b1m   = (const float*)d_in[4];
    const float* w1m_r = (const float*)d_in[5];
    const float* w1x_l = (const float*)d_in[6];
    const float* b1x   = (const float*)d_in[7];
    const float* w1x_r = (const float*)d_in[8];
    const float* w2m_l = (const float*)d_in[9];
    const float* b2m   = (const float*)d_in[10];
    const float* w2m_r = (const float*)d_in[11];
    const float* w2x_l = (const float*)d_in[12];
    const float* b2x   = (const float*)d_in[13];
    const float* w2x_r = (const float*)d_in[14];
    const float* w3    = (const float*)d_in[15];
    const float* b3    = (const float*)d_in[16];
    const float* w4    = (const float*)d_in[17];
    const float* b4    = (const float*)d_in[18];
    const float* w5    = (const float*)d_in[19];
    const float* b5    = (const float*)d_in[20];
    float* out = (float*)d_out;

    // CSR build
    k_zero_deg<<<(N_NODES + 255) / 256, 256>>>();
    k_count<<<(N_EDGES + 255) / 256, 256>>>(ei);
    k_scan1<<<NBLK, SCAN_B>>>();
    k_scan2<<<1, 128>>>();
    k_scan3<<<(N_NODES + SCAN_B - 1) / SCAN_B, SCAN_B>>>();
    k_scatter<<<(N_EDGES + 255) / 256, 256>>>(ei, norm);

    // GNN
    k_layer1<<<(N_NODES * 32 + 255) / 256, 256>>>(x, w1m_l, b1m, w1m_r, w1x_l, b1x, w1x_r);
    k_gather2<<<(N_NODES * 8 + 255) / 256, 256>>>();
    k_node2<<<(N_NODES + 127) / 128, 128>>>(w2m_l, b2m, w2m_r, w2x_l, b2x, w2x_r,
                                            w3, b3, w4, b4, w5, b5, out);
}